// round 5
// baseline (speedup 1.0000x reference)
#include <cuda_runtime.h>

// IFOPooling: h_t = f_t * h_{t-1} + i_t * z_t over S (contiguous), per (b,h) row.
// R4 body (affine-pair parallel scan, streaming hints) wrapped in a persistent
// grid-stride loop: 1216 blocks instead of 16384 to cut graph-replay launch
// overhead, with regs capped at 32 so occupancy matches the one-shot version.

constexpr int S_LEN = 2048;
constexpr int NTHR  = 256;
constexpr int PER   = S_LEN / NTHR;   // 8 elements per thread
constexpr int GRID  = 152 * 8;        // 1216 persistent CTAs

__global__ __launch_bounds__(NTHR, 8)
void ifo_scan_gs(const float* __restrict__ f,
                 const float* __restrict__ z,
                 const float* __restrict__ i_,
                 float* __restrict__ out,
                 int n_rows)
{
    const int t    = threadIdx.x;
    const int lane = t & 31;
    const int warp = t >> 5;

    __shared__ float sA[NTHR / 32];
    __shared__ float sB[NTHR / 32];

    // Incremental base: avoids 64-bit multiply per iteration.
    size_t base = (size_t)blockIdx.x * S_LEN + (size_t)t * PER;
    const size_t step = (size_t)GRID * S_LEN;

    for (int row = blockIdx.x; row < n_rows; row += GRID, base += step) {
        // ---- Load 8 contiguous elements of f, z, i (streaming) ----
        float4 fa = __ldcs(reinterpret_cast<const float4*>(f  + base));
        float4 fb = __ldcs(reinterpret_cast<const float4*>(f  + base + 4));
        float4 za = __ldcs(reinterpret_cast<const float4*>(z  + base));
        float4 zb = __ldcs(reinterpret_cast<const float4*>(z  + base + 4));
        float4 ia = __ldcs(reinterpret_cast<const float4*>(i_ + base));
        float4 ib = __ldcs(reinterpret_cast<const float4*>(i_ + base + 4));

        float fv[PER] = {fa.x, fa.y, fa.z, fa.w, fb.x, fb.y, fb.z, fb.w};
        float xv[PER] = {ia.x * za.x, ia.y * za.y, ia.z * za.z, ia.w * za.w,
                         ib.x * zb.x, ib.y * zb.y, ib.z * zb.z, ib.w * zb.w};

        // ---- Local chunk -> affine pair (A, B): h_out = A*h_in + B ----
        float A = 1.0f, Bc = 0.0f;
        #pragma unroll
        for (int j = 0; j < PER; j++) {
            Bc = fmaf(fv[j], Bc, xv[j]);
            A  = A * fv[j];
        }

        // ---- Intra-warp inclusive scan over pairs ----
        float Ai = A, Bi = Bc;
        #pragma unroll
        for (int d = 1; d < 32; d <<= 1) {
            float Au = __shfl_up_sync(0xffffffffu, Ai, d);
            float Bu = __shfl_up_sync(0xffffffffu, Bi, d);
            if (lane >= d) {
                Bi = fmaf(Ai, Bu, Bi);
                Ai = Ai * Au;
            }
        }

        // ---- Cross-warp prefix via shared memory ----
        __syncthreads();   // protect sA/sB reuse across loop iterations
        if (lane == 31) { sA[warp] = Ai; sB[warp] = Bi; }
        __syncthreads();

        float Aw = 1.0f, Bw = 0.0f;
        #pragma unroll
        for (int w = 0; w < NTHR / 32; w++) {
            if (w < warp) {
                Bw = fmaf(sA[w], Bw, sB[w]);
                Aw = Aw * sA[w];
            }
        }

        // ---- Thread's exclusive prefix within warp ----
        float Ae = __shfl_up_sync(0xffffffffu, Ai, 1);
        float Be = __shfl_up_sync(0xffffffffu, Bi, 1);
        if (lane == 0) { Ae = 1.0f; Be = 0.0f; }

        // Incoming h for this chunk (h0 = 0): h_in = Ae*Bw + Be
        float h = fmaf(Ae, Bw, Be);

        // ---- Replay chunk from registers, streaming stores ----
        float ov[PER];
        #pragma unroll
        for (int j = 0; j < PER; j++) {
            h = fmaf(fv[j], h, xv[j]);
            ov[j] = h;
        }

        __stcs(reinterpret_cast<float4*>(out + base),
               make_float4(ov[0], ov[1], ov[2], ov[3]));
        __stcs(reinterpret_cast<float4*>(out + base + 4),
               make_float4(ov[4], ov[5], ov[6], ov[7]));
    }
}

extern "C" void kernel_launch(void* const* d_in, const int* in_sizes, int n_in,
                              void* d_out, int out_size)
{
    const float* f = (const float*)d_in[0];
    const float* z = (const float*)d_in[1];
    const float* i = (const float*)d_in[2];
    float* out = (float*)d_out;

    const int n_rows = in_sizes[0] / S_LEN;   // B*H = 16384
    const int grid = (n_rows < GRID) ? n_rows : GRID;
    ifo_scan_gs<<<grid, NTHR>>>(f, z, i, out, n_rows);
}

// round 6
// speedup vs baseline: 1.2346x; 1.2346x over previous
#include <cuda_runtime.h>

// IFOPooling: h_t = f_t * h_{t-1} + i_t * z_t over S (contiguous), per (b,h) row.
// One CTA per row, 512 threads x 4 elements: shorter serial chains and full
// 2048-thread/SM occupancy vs the 256x8 variant. Loads first, single barrier,
// streaming cache hints (zero-reuse streams).

constexpr int S_LEN  = 2048;
constexpr int NTHR   = 512;
constexpr int PER    = S_LEN / NTHR;   // 4 elements per thread
constexpr int NWARP  = NTHR / 32;      // 16

__global__ __launch_bounds__(NTHR, 4)
void ifo_scan_kernel(const float* __restrict__ f,
                     const float* __restrict__ z,
                     const float* __restrict__ i_,
                     float* __restrict__ out)
{
    const int t    = threadIdx.x;
    const int lane = t & 31;
    const int warp = t >> 5;

    const size_t base = (size_t)blockIdx.x * S_LEN + (size_t)t * PER;

    // ---- One float4 from each stream (streaming / evict-first) ----
    float4 fa = __ldcs(reinterpret_cast<const float4*>(f  + base));
    float4 za = __ldcs(reinterpret_cast<const float4*>(z  + base));
    float4 ia = __ldcs(reinterpret_cast<const float4*>(i_ + base));

    float fv[PER] = {fa.x, fa.y, fa.z, fa.w};
    float xv[PER] = {ia.x * za.x, ia.y * za.y, ia.z * za.z, ia.w * za.w};

    // ---- Local chunk -> affine pair (A, B): h_out = A*h_in + B ----
    float A = 1.0f, Bc = 0.0f;
    #pragma unroll
    for (int j = 0; j < PER; j++) {
        Bc = fmaf(fv[j], Bc, xv[j]);
        A  = A * fv[j];
    }

    // ---- Intra-warp inclusive scan over pairs ----
    // combine(prev=(Ap,Bp), cur=(Ac,Bc)) = (Ap*Ac, Ac*Bp + Bc)
    float Ai = A, Bi = Bc;
    #pragma unroll
    for (int d = 1; d < 32; d <<= 1) {
        float Au = __shfl_up_sync(0xffffffffu, Ai, d);
        float Bu = __shfl_up_sync(0xffffffffu, Bi, d);
        if (lane >= d) {
            Bi = fmaf(Ai, Bu, Bi);
            Ai = Ai * Au;
        }
    }

    // ---- Cross-warp prefix via shared memory (16 warps, one barrier) ----
    __shared__ float sA[NWARP];
    __shared__ float sB[NWARP];
    if (lane == 31) { sA[warp] = Ai; sB[warp] = Bi; }
    __syncthreads();

    // Exclusive prefix over warps; only the B component is needed (h0 = 0).
    float Bw = 0.0f;
    #pragma unroll
    for (int w = 0; w < NWARP; w++) {
        if (w < warp) {
            Bw = fmaf(sA[w], Bw, sB[w]);
        }
    }

    // ---- Thread's exclusive prefix within warp ----
    float Ae = __shfl_up_sync(0xffffffffu, Ai, 1);
    float Be = __shfl_up_sync(0xffffffffu, Bi, 1);
    if (lane == 0) { Ae = 1.0f; Be = 0.0f; }

    // Incoming h for this chunk (h0 = 0): h_in = Ae*Bw + Be
    float h = fmaf(Ae, Bw, Be);

    // ---- Replay chunk from registers, streaming store ----
    float ov[PER];
    #pragma unroll
    for (int j = 0; j < PER; j++) {
        h = fmaf(fv[j], h, xv[j]);
        ov[j] = h;
    }

    __stcs(reinterpret_cast<float4*>(out + base),
           make_float4(ov[0], ov[1], ov[2], ov[3]));
}

extern "C" void kernel_launch(void* const* d_in, const int* in_sizes, int n_in,
                              void* d_out, int out_size)
{
    const float* f = (const float*)d_in[0];
    const float* z = (const float*)d_in[1];
    const float* i = (const float*)d_in[2];
    float* out = (float*)d_out;

    const int n_rows = in_sizes[0] / S_LEN;   // B*H = 16384
    ifo_scan_kernel<<<n_rows, NTHR>>>(f, z, i, out);
}